// round 16
// baseline (speedup 1.0000x reference)
#include <cuda_runtime.h>
#include <math.h>
#include <float.h>

#define Tn   512
#define Bn   64
#define En   256
#define Hn   512
#define G4   2048
#define NBLK 128
#define NTHR 256
#define NGRP 4
#define GBLK 32            // blocks per group
#define GB   16            // batches per group

// Scratch (device globals: the sanctioned alloc-free scratch mechanism)
__device__ float    g_xg[(size_t)Tn * G4 * Bn];    // [t][j][b]  256 MB
__device__ float    g_h[2][NGRP * Hn * GB];        // ping-pong, [grp][k][bl]
__device__ float    g_feat[Hn * Bn];               // [hidx][b]
__device__ unsigned g_count[NGRP * 32];            // per-group arrivals (padded)
__device__ unsigned g_gen[NGRP * 32];              // per-group generation

// ---------------------------------------------------------------------------
// Scoped memory ops (cross-SM data traffic is L2-scoped: STG + cp.async.cg).
// ---------------------------------------------------------------------------
__device__ __forceinline__ unsigned ld_relaxed_gpu(const unsigned* p) {
    unsigned v;
    asm volatile("ld.relaxed.gpu.global.u32 %0, [%1];" : "=r"(v) : "l"(p));
    return v;
}
__device__ __forceinline__ unsigned ld_acquire_gpu(const unsigned* p) {
    unsigned v;
    asm volatile("ld.acquire.gpu.global.u32 %0, [%1];" : "=r"(v) : "l"(p));
    return v;
}
__device__ __forceinline__ unsigned atom_add_release_gpu(unsigned* p, unsigned v) {
    unsigned old;
    asm volatile("atom.add.release.gpu.global.u32 %0, [%1], %2;"
                 : "=r"(old) : "l"(p), "r"(v));
    return old;
}
__device__ __forceinline__ void st_relaxed_gpu(unsigned* p, unsigned v) {
    asm volatile("st.relaxed.gpu.global.u32 [%0], %1;" :: "l"(p), "r"(v));
}
__device__ __forceinline__ void st_release_gpu(unsigned* p, unsigned v) {
    asm volatile("st.release.gpu.global.u32 [%0], %1;" :: "l"(p), "r"(v));
}

__device__ __forceinline__ void cp_async16(void* s, const void* g) {
    unsigned saddr = (unsigned)__cvta_generic_to_shared(s);
    asm volatile("cp.async.cg.shared.global [%0], [%1], 16;"
                 :: "r"(saddr), "l"(g));
}
#define CP_COMMIT() asm volatile("cp.async.commit_group;")
#define CP_WAIT(N)  asm volatile("cp.async.wait_group %0;" :: "n"(N))

// Packed fp32x2 ops (exact fp32 semantics).
__device__ __forceinline__ unsigned long long ffma2(unsigned long long a,
                                                    unsigned long long b,
                                                    unsigned long long c) {
    unsigned long long d;
    asm("fma.rn.f32x2 %0, %1, %2, %3;" : "=l"(d) : "l"(a), "l"(b), "l"(c));
    return d;
}
__device__ __forceinline__ unsigned long long addf2(unsigned long long a,
                                                    unsigned long long b) {
    unsigned long long d;
    asm("add.rn.f32x2 %0, %1, %2;" : "=l"(d) : "l"(a), "l"(b));
    return d;
}
__device__ __forceinline__ unsigned long long dup2(float x) {
    unsigned long long d;
    asm("mov.b64 %0, {%1, %1};" : "=l"(d) : "f"(x));
    return d;
}

// Fast, accurate-enough transcendentals (MUFU-based, ~1e-7 rel err).
__device__ __forceinline__ float sigf(float x) {
    return 1.f / (1.f + __expf(-x));
}
__device__ __forceinline__ float tanhf_fast(float x) {
    return 2.f / (1.f + __expf(-2.f * x)) - 1.f;
}

// ---------------------------------------------------------------------------
// Per-GROUP generation barrier (32 co-resident blocks per group).
// ---------------------------------------------------------------------------
__device__ __forceinline__ void group_barrier(int grp) {
    __syncthreads();
    if (threadIdx.x == 0) {
        unsigned* cnt = &g_count[grp * 32];
        unsigned* gen = &g_gen[grp * 32];
        const unsigned cur = ld_relaxed_gpu(gen);
        if (atom_add_release_gpu(cnt, 1u) == GBLK - 1) {
            st_relaxed_gpu(cnt, 0u);
            st_release_gpu(gen, cur + 1u);   // release orders the reset too
        } else {
            while (ld_acquire_gpu(gen) == cur) {}
        }
    }
    __syncthreads();
}

// ---------------------------------------------------------------------------
// Kernel 1: fused embedding gather + input projection GEMM, f32x2 inner loop,
// with __launch_bounds__(256, 2): forces regs <= 128 so TWO blocks/SM stay
// resident (R14's 138-reg build silently halved occupancy — that, not the
// smem, was the regression). W_ih duplicated in smem ({w,w} pairs); e-pairs
// free from the float4 bit pattern. Per k: 5 LDS.128 + 16 FFMA2.
// Smem 43KB x 2 blocks = 86KB < 227KB cap.
// ---------------------------------------------------------------------------
#define SWW 264   // floats per k-row of duplicated W (256 + pad), 16B-aligned

__global__ __launch_bounds__(256, 2)
void embed_gemm_kernel(const int*   __restrict__ x,
                       const float* __restrict__ emb,
                       const float* __restrict__ Wih,
                       const float* __restrict__ bih,
                       const float* __restrict__ bhh) {
    __shared__ float sW2[32][SWW];  // [k][j*2 {dup}]
    __shared__ float sE[32][68];    // [k][b]
    __shared__ int   sTok[Bn];

    const int tid   = threadIdx.x;
    const int jBase = blockIdx.x * 128;
    const int t     = blockIdx.y;

    if (tid < Bn) sTok[tid] = x[tid * Tn + t];
    __syncthreads();

    const int tb = tid & 15;    // b-group (4 batches = 2 pairs)
    const int tj = tid >> 4;    // j-group (8 rows)

    unsigned long long acc2[8][2];
#pragma unroll
    for (int jj = 0; jj < 8; ++jj) { acc2[jj][0] = 0ull; acc2[jj][1] = 0ull; }

    for (int kc = 0; kc < En; kc += 32) {
#pragma unroll
        for (int i = 0; i < 16; ++i) {                 // 128x32 W chunk (dup)
            int idx = tid + i * 256;
            int k = idx & 31, j = idx >> 5;
            const float v = Wih[(size_t)(jBase + j) * En + kc + k];
            sW2[k][j * 2 + 0] = v;
            sW2[k][j * 2 + 1] = v;
        }
#pragma unroll
        for (int i = 0; i < 8; ++i) {                  // 64x32 emb chunk (gathered)
            int idx = tid + i * 256;
            int k = idx & 31, b = idx >> 5;
            sE[k][b] = emb[(size_t)sTok[b] * En + kc + k];
        }
        __syncthreads();

#pragma unroll
        for (int k = 0; k < 32; ++k) {
            const ulonglong2 e2 =
                *reinterpret_cast<const ulonglong2*>(&sE[k][tb * 4]);
            const float* wb = &sW2[k][tj * 16];
            const ulonglong2 wd0 = *reinterpret_cast<const ulonglong2*>(wb + 0);
            const ulonglong2 wd1 = *reinterpret_cast<const ulonglong2*>(wb + 4);
            const ulonglong2 wd2 = *reinterpret_cast<const ulonglong2*>(wb + 8);
            const ulonglong2 wd3 = *reinterpret_cast<const ulonglong2*>(wb + 12);
            acc2[0][0] = ffma2(wd0.x, e2.x, acc2[0][0]);
            acc2[0][1] = ffma2(wd0.x, e2.y, acc2[0][1]);
            acc2[1][0] = ffma2(wd0.y, e2.x, acc2[1][0]);
            acc2[1][1] = ffma2(wd0.y, e2.y, acc2[1][1]);
            acc2[2][0] = ffma2(wd1.x, e2.x, acc2[2][0]);
            acc2[2][1] = ffma2(wd1.x, e2.y, acc2[2][1]);
            acc2[3][0] = ffma2(wd1.y, e2.x, acc2[3][0]);
            acc2[3][1] = ffma2(wd1.y, e2.y, acc2[3][1]);
            acc2[4][0] = ffma2(wd2.x, e2.x, acc2[4][0]);
            acc2[4][1] = ffma2(wd2.x, e2.y, acc2[4][1]);
            acc2[5][0] = ffma2(wd2.y, e2.x, acc2[5][0]);
            acc2[5][1] = ffma2(wd2.y, e2.y, acc2[5][1]);
            acc2[6][0] = ffma2(wd3.x, e2.x, acc2[6][0]);
            acc2[6][1] = ffma2(wd3.x, e2.y, acc2[6][1]);
            acc2[7][0] = ffma2(wd3.y, e2.x, acc2[7][0]);
            acc2[7][1] = ffma2(wd3.y, e2.y, acc2[7][1]);
        }
        __syncthreads();
    }

    float* xg_t = g_xg + (size_t)t * (G4 * Bn);
#pragma unroll
    for (int jj = 0; jj < 8; ++jj) {
        const int j = jBase + tj * 8 + jj;
        const float bias = bih[j] + bhh[j];
        float a0, a1, a2, a3;
        asm("mov.b64 {%0, %1}, %2;" : "=f"(a0), "=f"(a1) : "l"(acc2[jj][0]));
        asm("mov.b64 {%0, %1}, %2;" : "=f"(a2), "=f"(a3) : "l"(acc2[jj][1]));
        float4 v = make_float4(a0 + bias, a1 + bias, a2 + bias, a3 + bias);
        *reinterpret_cast<float4*>(&xg_t[(size_t)j * Bn + tb * 4]) = v;
    }
}

// ---------------------------------------------------------------------------
// Kernel 2: persistent LSTM, batch-grouped (4 groups x 32 blocks x 16 batches)
// — R14 winner, UNCHANGED. Dot: thread = (ks in 4, hl in 16, bq in 4).
// Per k: LDS.128 W{i,f,g,o} + LDS.128 h[4b] + 4 dup-movs + 8 FFMA2 =
// 16 MACs / 2 crossbar wavefronts. 4-way k-split within each staged chunk;
// partials via 16KB sP; register-local epilogue + max-pool.
// Dynamic smem: sH 32KB + sW 128KB + sXg 8KB + sP 16KB = 184KB
// ---------------------------------------------------------------------------
#define LSTM_SMEM ((Hn * GB + Hn * 64 + 2 * 64 * GB + 4096) * (int)sizeof(float))

__global__ __launch_bounds__(NTHR, 1)
void lstm_kernel(const float* __restrict__ Whh,
                 const int*   __restrict__ length) {
    extern __shared__ float sm[];
    float* sH   = sm;                    // [k][bl]            512*16
    float* sW   = sH + Hn * GB;          // [k][hl*4+g]        512*64
    float* sXg  = sW + Hn * 64;          // [2][g*16+hl][bl]   2*64*16
    float* sPif = sXg + 2 * 64 * GB;     // ull [ks][hl][b]    1024 ull
    float* sPgo = sPif + 2048;           // ull [ks][hl][b]    1024 ull

    const int tid  = threadIdx.x;
    const int grp  = blockIdx.x >> 5;          // group (0..3)
    const int q    = blockIdx.x & 31;          // block-in-group
    const int hrow = q * GB;                   // first owned h index
    const int bbase = grp * GB;                // first owned batch

    // Dot mapping
    const int ks = tid >> 6;           // k quarter within chunk (0..3)
    const int hl = (tid >> 2) & 15;    // local h index (0..15)
    const int bq = tid & 3;            // batch quad (0..3) -> b = 4bq..4bq+3

    // Epilogue mapping
    const int eh = tid >> 4;           // local h index (0..15)
    const int eb = tid & 15;           // local batch  (0..15)

    // Load this block's 64 W_hh rows: sW[k*64 + hl*4 + g] (one-time).
#pragma unroll
    for (int r = 0; r < 64; ++r) {
        const int g = r & 3, h2 = r >> 2;
        const float* src = Whh + (size_t)(g * Hn + hrow + h2) * Hn;
        for (int k = tid; k < Hn; k += NTHR)
            sW[k * 64 + h2 * 4 + g] = src[k];
    }
    // Zero this block's h slice in buffer 0.
    {
        const int r = tid >> 4, c = tid & 15;
        g_h[0][(grp * Hn + hrow + r) * GB + c] = 0.f;
    }

    // Prefetch xg slice for t=0: 64 rows (g*16+hl) x 16 batches = 4 KB.
    {
        const int r = tid >> 2, seg = tid & 3;   // 64 rows x 4 segs (16B)
        const int g = r >> 4, h2 = r & 15;
        const float* src = g_xg + (size_t)(g * Hn + hrow + h2) * Bn
                         + bbase + seg * 4;
        cp_async16(&sXg[r * GB + seg * 4], src);
        CP_COMMIT();
    }

    float c_state = 0.f;
    float maxv    = -FLT_MAX;
    const int mylen = length[bbase + eb];

    group_barrier(grp);   // release covers the h-slice zeroing

    for (int t = 0; t < Tn; ++t) {
        const float* hsrc = g_h[t & 1] + grp * (Hn * GB);
        float*       hdst = g_h[(t + 1) & 1] + grp * (Hn * GB);
        const float* xgCur = sXg + (t & 1) * (64 * GB);
        float*       xgNxt = sXg + ((t + 1) & 1) * (64 * GB);

        // Issue: 4 h-chunk groups (8 KB each) + xg[t+1] prefetch group.
#pragma unroll
        for (int c = 0; c < 4; ++c) {
            const float* gsrc = hsrc + c * (128 * GB);
            float*       sdst = sH   + c * (128 * GB);
#pragma unroll
            for (int j = 0; j < 2; ++j) {
                const int i = tid + j * NTHR;      // 512 16B segs / chunk
                cp_async16(sdst + i * 4, gsrc + i * 4);
            }
            CP_COMMIT();
        }
        {
            const int tn = (t + 1 < Tn) ? t + 1 : t;
            const int r = tid >> 2, seg = tid & 3;
            const int g = r >> 4, h2 = r & 15;
            const float* src = g_xg + (size_t)tn * (G4 * Bn)
                             + (size_t)(g * Hn + hrow + h2) * Bn
                             + bbase + seg * 4;
            cp_async16(xgNxt + r * GB + seg * 4, src);
            CP_COMMIT();
        }

        // 4 batches x {i,f}/{g,o} packed accumulators.
        unsigned long long aIF[4] = {0ull, 0ull, 0ull, 0ull};
        unsigned long long aGO[4] = {0ull, 0ull, 0ull, 0ull};

        // Pipelined dot: every warp works on every chunk (k-split ks inside).
#pragma unroll
        for (int c = 0; c < 4; ++c) {
            if (c == 0)      { CP_WAIT(4); }   // retires xg[t] + chunk0
            else if (c == 1) { CP_WAIT(3); }
            else if (c == 2) { CP_WAIT(2); }
            else             { CP_WAIT(1); }   // leaves xg[t+1] pending
            __syncthreads();

            const float* pH = sH + c * (128 * GB) + ks * (32 * GB) + bq * 4;
            const float* pW = sW + (c * 128 + ks * 32) * 64 + hl * 4;
#pragma unroll 8
            for (int k = 0; k < 32; ++k) {
                const float4 hv = *reinterpret_cast<const float4*>(pH + k * GB);
                const ulonglong2 w2 =
                    *reinterpret_cast<const ulonglong2*>(pW + k * 64);
                const unsigned long long h0 = dup2(hv.x);
                const unsigned long long h1 = dup2(hv.y);
                const unsigned long long h2d = dup2(hv.z);
                const unsigned long long h3 = dup2(hv.w);
                aIF[0] = ffma2(w2.x, h0, aIF[0]);
                aGO[0] = ffma2(w2.y, h0, aGO[0]);
                aIF[1] = ffma2(w2.x, h1, aIF[1]);
                aGO[1] = ffma2(w2.y, h1, aGO[1]);
                aIF[2] = ffma2(w2.x, h2d, aIF[2]);
                aGO[2] = ffma2(w2.y, h2d, aGO[2]);
                aIF[3] = ffma2(w2.x, h3, aIF[3]);
                aGO[3] = ffma2(w2.y, h3, aGO[3]);
            }
        }

        // Store partials: sPif/sPgo ull at [ks][hl][b].
        {
            unsigned long long* pif =
                reinterpret_cast<unsigned long long*>(sPif)
                + (ks * 16 + hl) * 16 + bq * 4;
            unsigned long long* pgo =
                reinterpret_cast<unsigned long long*>(sPgo)
                + (ks * 16 + hl) * 16 + bq * 4;
#pragma unroll
            for (int j = 0; j < 4; ++j) { pif[j] = aIF[j]; pgo[j] = aGO[j]; }
        }
        __syncthreads();

        // Epilogue: thread (eh, eb) sums 4 k-quarter partials (packed adds).
        {
            const unsigned long long* pif =
                reinterpret_cast<const unsigned long long*>(sPif) + eh * 16 + eb;
            const unsigned long long* pgo =
                reinterpret_cast<const unsigned long long*>(sPgo) + eh * 16 + eb;
            unsigned long long sIF = addf2(addf2(pif[0], pif[256]),
                                           addf2(pif[512], pif[768]));
            unsigned long long sGO = addf2(addf2(pgo[0], pgo[256]),
                                           addf2(pgo[512], pgo[768]));
            float ai, af, ag, ao;
            asm("mov.b64 {%0, %1}, %2;" : "=f"(ai), "=f"(af) : "l"(sIF));
            asm("mov.b64 {%0, %1}, %2;" : "=f"(ag), "=f"(ao) : "l"(sGO));
            const float gi = xgCur[(0 * 16 + eh) * GB + eb] + ai;
            const float gf = xgCur[(1 * 16 + eh) * GB + eb] + af;
            const float gg = xgCur[(2 * 16 + eh) * GB + eb] + ag;
            const float go = xgCur[(3 * 16 + eh) * GB + eb] + ao;
            const float is = sigf(gi);
            const float fs = sigf(gf);
            const float gt = tanhf_fast(gg);
            const float os = sigf(go);
            c_state = fs * c_state + is * gt;
            const float h = os * tanhf_fast(c_state);
            hdst[(hrow + eh) * GB + eb] = h;
            if (t < mylen) maxv = fmaxf(maxv, h);
        }
        group_barrier(grp);   // release-arrive orders the h store
    }

    g_feat[(hrow + eh) * Bn + bbase + eb] = maxv;
}

// ---------------------------------------------------------------------------
// Kernel 3: classifier  out[b][c] = sum_h feat[h][b] * W_cls[c][h] + b_cls[c]
// ---------------------------------------------------------------------------
__global__ void cls_kernel(const float* __restrict__ Wcls,
                           const float* __restrict__ bcls,
                           float* __restrict__ out) {
    const int tid = threadIdx.x;   // 128 threads
    const int b = tid >> 1, c = tid & 1;
    float s = bcls[c];
#pragma unroll 8
    for (int h = 0; h < Hn; ++h)
        s += g_feat[h * Bn + b] * Wcls[c * Hn + h];
    out[b * 2 + c] = s;
}

// ---------------------------------------------------------------------------
extern "C" void kernel_launch(void* const* d_in, const int* in_sizes, int n_in,
                              void* d_out, int out_size) {
    const int*   x      = (const int*)  d_in[0];  // [64,512] int32
    const int*   length = (const int*)  d_in[1];  // [64,1]   int32
    const float* emb    = (const float*)d_in[2];  // [32000,256]
    const float* Wih    = (const float*)d_in[3];  // [2048,256]
    const float* Whh    = (const float*)d_in[4];  // [2048,512]
    const float* bih    = (const float*)d_in[5];  // [2048]
    const float* bhh    = (const float*)d_in[6];  // [2048]
    const float* Wcls   = (const float*)d_in[7];  // [2,512]
    const float* bcls   = (const float*)d_in[8];  // [2]
    float* out = (float*)d_out;                   // [64,2]

    cudaFuncSetAttribute(lstm_kernel,
                         cudaFuncAttributeMaxDynamicSharedMemorySize, LSTM_SMEM);

    embed_gemm_kernel<<<dim3(16, Tn), 256>>>(x, emb, Wih, bih, bhh);
    lstm_kernel<<<NBLK, NTHR, LSTM_SMEM>>>(Whh, length);
    cls_kernel<<<1, 128>>>(Wcls, bcls, out);
    (void)in_sizes; (void)n_in; (void)out_size;
}

// round 17
// speedup vs baseline: 1.0724x; 1.0724x over previous
#include <cuda_runtime.h>
#include <math.h>
#include <float.h>

#define Tn   512
#define Bn   64
#define En   256
#define Hn   512
#define G4   2048
#define NBLK 128
#define NTHR 256
#define NGRP 4
#define GBLK 32            // blocks per group
#define GB   16            // batches per group

// Scratch (device globals: the sanctioned alloc-free scratch mechanism)
__device__ float    g_xg[(size_t)Tn * G4 * Bn];    // [t][j][b]  256 MB
__device__ float    g_h[2][NGRP * Hn * GB];        // ping-pong, [grp][k][bl]
__device__ float    g_feat[Hn * Bn];               // [hidx][b]
__device__ unsigned g_count[NGRP * 32];            // init-barrier arrivals
__device__ unsigned g_gen[NGRP * 32];              // init-barrier generation
__device__ unsigned g_flag[NGRP * GBLK * 32];      // per-block step flags
                                                   // (own 128B line each)

// ---------------------------------------------------------------------------
// Scoped memory ops (cross-SM data traffic is L2-scoped: STG + cp.async.cg).
// ---------------------------------------------------------------------------
__device__ __forceinline__ unsigned ld_relaxed_gpu(const unsigned* p) {
    unsigned v;
    asm volatile("ld.relaxed.gpu.global.u32 %0, [%1];" : "=r"(v) : "l"(p));
    return v;
}
__device__ __forceinline__ unsigned ld_acquire_gpu(const unsigned* p) {
    unsigned v;
    asm volatile("ld.acquire.gpu.global.u32 %0, [%1];" : "=r"(v) : "l"(p));
    return v;
}
__device__ __forceinline__ unsigned atom_add_release_gpu(unsigned* p, unsigned v) {
    unsigned old;
    asm volatile("atom.add.release.gpu.global.u32 %0, [%1], %2;"
                 : "=r"(old) : "l"(p), "r"(v));
    return old;
}
__device__ __forceinline__ void st_relaxed_gpu(unsigned* p, unsigned v) {
    asm volatile("st.relaxed.gpu.global.u32 [%0], %1;" :: "l"(p), "r"(v));
}
__device__ __forceinline__ void st_release_gpu(unsigned* p, unsigned v) {
    asm volatile("st.release.gpu.global.u32 [%0], %1;" :: "l"(p), "r"(v));
}

__device__ __forceinline__ void cp_async16(void* s, const void* g) {
    unsigned saddr = (unsigned)__cvta_generic_to_shared(s);
    asm volatile("cp.async.cg.shared.global [%0], [%1], 16;"
                 :: "r"(saddr), "l"(g));
}
#define CP_COMMIT() asm volatile("cp.async.commit_group;")
#define CP_WAIT(N)  asm volatile("cp.async.wait_group %0;" :: "n"(N))

// Packed fp32x2 ops (exact fp32 semantics).
__device__ __forceinline__ unsigned long long ffma2(unsigned long long a,
                                                    unsigned long long b,
                                                    unsigned long long c) {
    unsigned long long d;
    asm("fma.rn.f32x2 %0, %1, %2, %3;" : "=l"(d) : "l"(a), "l"(b), "l"(c));
    return d;
}
__device__ __forceinline__ unsigned long long addf2(unsigned long long a,
                                                    unsigned long long b) {
    unsigned long long d;
    asm("add.rn.f32x2 %0, %1, %2;" : "=l"(d) : "l"(a), "l"(b));
    return d;
}
__device__ __forceinline__ unsigned long long dup2(float x) {
    unsigned long long d;
    asm("mov.b64 %0, {%1, %1};" : "=l"(d) : "f"(x));
    return d;
}

// Fast, accurate-enough transcendentals (MUFU-based, ~1e-7 rel err).
__device__ __forceinline__ float sigf(float x) {
    return 1.f / (1.f + __expf(-x));
}
__device__ __forceinline__ float tanhf_fast(float x) {
    return 2.f / (1.f + __expf(-2.f * x)) - 1.f;
}

// ---------------------------------------------------------------------------
// Per-GROUP generation barrier — used ONCE at init (covers zero-init + W).
// ---------------------------------------------------------------------------
__device__ __forceinline__ void group_barrier(int grp) {
    __syncthreads();
    if (threadIdx.x == 0) {
        unsigned* cnt = &g_count[grp * 32];
        unsigned* gen = &g_gen[grp * 32];
        const unsigned cur = ld_relaxed_gpu(gen);
        if (atom_add_release_gpu(cnt, 1u) == GBLK - 1) {
            st_relaxed_gpu(cnt, 0u);
            st_release_gpu(gen, cur + 1u);
        } else {
            while (ld_acquire_gpu(gen) == cur) {}
        }
    }
    __syncthreads();
}

// ---------------------------------------------------------------------------
// Kernel 1: fused embedding gather + input projection GEMM — scalar version
// (f32x2 variants lose: duplicated-W doubles smem crossbar wavefronts; this
// kernel is crossbar/issue-bound, not FMA-slot-bound. Proven 2 blocks/SM.)
// ---------------------------------------------------------------------------
__global__ __launch_bounds__(256)
void embed_gemm_kernel(const int*   __restrict__ x,
                       const float* __restrict__ emb,
                       const float* __restrict__ Wih,
                       const float* __restrict__ bih,
                       const float* __restrict__ bhh) {
    __shared__ float sW[32][132];   // [k][j], pad keeps float4 alignment
    __shared__ float sE[32][68];    // [k][b]
    __shared__ int   sTok[Bn];

    const int tid   = threadIdx.x;
    const int jBase = blockIdx.x * 128;
    const int t     = blockIdx.y;

    if (tid < Bn) sTok[tid] = x[tid * Tn + t];
    __syncthreads();

    const int tb = tid & 15;    // b-group (4 batches)
    const int tj = tid >> 4;    // j-group (8 rows)

    float acc[8][4];
#pragma unroll
    for (int jj = 0; jj < 8; ++jj)
#pragma unroll
        for (int bb = 0; bb < 4; ++bb) acc[jj][bb] = 0.f;

    for (int kc = 0; kc < En; kc += 32) {
#pragma unroll
        for (int i = 0; i < 16; ++i) {                 // 128x32 W chunk
            int idx = tid + i * 256;
            int k = idx & 31, j = idx >> 5;
            sW[k][j] = Wih[(size_t)(jBase + j) * En + kc + k];
        }
#pragma unroll
        for (int i = 0; i < 8; ++i) {                  // 64x32 emb chunk (gathered)
            int idx = tid + i * 256;
            int k = idx & 31, b = idx >> 5;
            sE[k][b] = emb[(size_t)sTok[b] * En + kc + k];
        }
        __syncthreads();

#pragma unroll
        for (int k = 0; k < 32; ++k) {
            const float4 ev = *reinterpret_cast<const float4*>(&sE[k][tb * 4]);
            const float4 wa = *reinterpret_cast<const float4*>(&sW[k][tj * 8]);
            const float4 wb = *reinterpret_cast<const float4*>(&sW[k][tj * 8 + 4]);
            const float e4[4] = {ev.x, ev.y, ev.z, ev.w};
            const float w8[8] = {wa.x, wa.y, wa.z, wa.w, wb.x, wb.y, wb.z, wb.w};
#pragma unroll
            for (int jj = 0; jj < 8; ++jj)
#pragma unroll
                for (int bb = 0; bb < 4; ++bb)
                    acc[jj][bb] += w8[jj] * e4[bb];
        }
        __syncthreads();
    }

    float* xg_t = g_xg + (size_t)t * (G4 * Bn);
#pragma unroll
    for (int jj = 0; jj < 8; ++jj) {
        const int j = jBase + tj * 8 + jj;
        const float bias = bih[j] + bhh[j];
        float4 v = make_float4(acc[jj][0] + bias, acc[jj][1] + bias,
                               acc[jj][2] + bias, acc[jj][3] + bias);
        *reinterpret_cast<float4*>(&xg_t[(size_t)j * Bn + tb * 4]) = v;
    }
}

// ---------------------------------------------------------------------------
// Kernel 2: persistent LSTM, batch-grouped. R14 dot UNCHANGED.
// NEW sync: the per-step counting barrier is replaced by per-block
// release-flags (free-running step counters, one 128B line per block).
// Producer: after the epilogue h-store + one __syncthreads, thread 0 does
// st.release flag = base+t+1. Consumer: warp 0 (lane=producer idx) ballot-
// polls all 32 group flags >= base+t BEFORE staging step t's h. Skew is
// naturally capped at 1 step, so the 2-buffer ping-pong stays sound; base
// is captured from the block's own flag so graph replays are safe.
// Dynamic smem: sH 32KB + sW 128KB + sXg 8KB + sP 16KB = 184KB
// ---------------------------------------------------------------------------
#define LSTM_SMEM ((Hn * GB + Hn * 64 + 2 * 64 * GB + 4096) * (int)sizeof(float))

__global__ __launch_bounds__(NTHR, 1)
void lstm_kernel(const float* __restrict__ Whh,
                 const int*   __restrict__ length) {
    extern __shared__ float sm[];
    float* sH   = sm;                    // [k][bl]            512*16
    float* sW   = sH + Hn * GB;          // [k][hl*4+g]        512*64
    float* sXg  = sW + Hn * 64;          // [2][g*16+hl][bl]   2*64*16
    float* sPif = sXg + 2 * 64 * GB;     // ull [ks][hl][b]    1024 ull
    float* sPgo = sPif + 2048;           // ull [ks][hl][b]    1024 ull

    const int tid  = threadIdx.x;
    const int grp  = blockIdx.x >> 5;          // group (0..3)
    const int q    = blockIdx.x & 31;          // block-in-group
    const int hrow = q * GB;                   // first owned h index
    const int bbase = grp * GB;                // first owned batch

    // Dot mapping
    const int ks = tid >> 6;           // k quarter within chunk (0..3)
    const int hl = (tid >> 2) & 15;    // local h index (0..15)
    const int bq = tid & 3;            // batch quad (0..3)

    // Epilogue mapping
    const int eh = tid >> 4;           // local h index (0..15)
    const int eb = tid & 15;           // local batch  (0..15)

    unsigned* myflag = &g_flag[(grp * GBLK + q) * 32];
    unsigned* grpflags = &g_flag[grp * GBLK * 32];
    // base: all flags in the system are equal at launch (each replay adds
    // exactly Tn to every flag). Reading our own is race-free.
    const unsigned base = ld_relaxed_gpu(myflag);

    // Load this block's 64 W_hh rows: sW[k*64 + hl*4 + g] (one-time).
#pragma unroll
    for (int r = 0; r < 64; ++r) {
        const int g = r & 3, h2 = r >> 2;
        const float* src = Whh + (size_t)(g * Hn + hrow + h2) * Hn;
        for (int k = tid; k < Hn; k += NTHR)
            sW[k * 64 + h2 * 4 + g] = src[k];
    }
    // Zero this block's h slice in buffer 0.
    {
        const int r = tid >> 4, c = tid & 15;
        g_h[0][(grp * Hn + hrow + r) * GB + c] = 0.f;
    }

    // Prefetch xg slice for t=0: 64 rows (g*16+hl) x 16 batches = 4 KB.
    {
        const int r = tid >> 2, seg = tid & 3;   // 64 rows x 4 segs (16B)
        const int g = r >> 4, h2 = r & 15;
        const float* src = g_xg + (size_t)(g * Hn + hrow + h2) * Bn
                         + bbase + seg * 4;
        cp_async16(&sXg[r * GB + seg * 4], src);
        CP_COMMIT();
    }

    float c_state = 0.f;
    float maxv    = -FLT_MAX;
    const int mylen = length[bbase + eb];

    group_barrier(grp);   // ONE-TIME: covers zero-init + base capture skew

    for (int t = 0; t < Tn; ++t) {
        const float* hsrc = g_h[t & 1] + grp * (Hn * GB);
        float*       hdst = g_h[(t + 1) & 1] + grp * (Hn * GB);
        const float* xgCur = sXg + (t & 1) * (64 * GB);
        float*       xgNxt = sXg + ((t + 1) & 1) * (64 * GB);

        // Wait for all 32 producers of h[t] (skips t=0: flags >= base).
        if (t > 0) {
            if (tid < GBLK) {
                const unsigned tgt = base + (unsigned)t;
                while (ld_acquire_gpu(&grpflags[tid * 32]) < tgt) {}
            }
            __syncthreads();   // publishes the acquires block-wide
        }

        // Issue: 4 h-chunk groups (8 KB each) + xg[t+1] prefetch group.
#pragma unroll
        for (int c = 0; c < 4; ++c) {
            const float* gsrc = hsrc + c * (128 * GB);
            float*       sdst = sH   + c * (128 * GB);
#pragma unroll
            for (int j = 0; j < 2; ++j) {
                const int i = tid + j * NTHR;      // 512 16B segs / chunk
                cp_async16(sdst + i * 4, gsrc + i * 4);
            }
            CP_COMMIT();
        }
        {
            const int tn = (t + 1 < Tn) ? t + 1 : t;
            const int r = tid >> 2, seg = tid & 3;
            const int g = r >> 4, h2 = r & 15;
            const float* src = g_xg + (size_t)tn * (G4 * Bn)
                             + (size_t)(g * Hn + hrow + h2) * Bn
                             + bbase + seg * 4;
            cp_async16(xgNxt + r * GB + seg * 4, src);
            CP_COMMIT();
        }

        // 4 batches x {i,f}/{g,o} packed accumulators.
        unsigned long long aIF[4] = {0ull, 0ull, 0ull, 0ull};
        unsigned long long aGO[4] = {0ull, 0ull, 0ull, 0ull};

        // Pipelined dot: every warp works on every chunk (k-split ks inside).
#pragma unroll
        for (int c = 0; c < 4; ++c) {
            if (c == 0)      { CP_WAIT(4); }   // retires xg[t] + chunk0
            else if (c == 1) { CP_WAIT(3); }
            else if (c == 2) { CP_WAIT(2); }
            else             { CP_WAIT(1); }   // leaves xg[t+1] pending
            __syncthreads();

            const float* pH = sH + c * (128 * GB) + ks * (32 * GB) + bq * 4;
            const float* pW = sW + (c * 128 + ks * 32) * 64 + hl * 4;
#pragma unroll 8
            for (int k = 0; k < 32; ++k) {
                const float4 hv = *reinterpret_cast<const float4*>(pH + k * GB);
                const ulonglong2 w2 =
                    *reinterpret_cast<const ulonglong2*>(pW + k * 64);
                const unsigned long long h0 = dup2(hv.x);
                const unsigned long long h1 = dup2(hv.y);
                const unsigned long long h2d = dup2(hv.z);
                const unsigned long long h3 = dup2(hv.w);
                aIF[0] = ffma2(w2.x, h0, aIF[0]);
                aGO[0] = ffma2(w2.y, h0, aGO[0]);
                aIF[1] = ffma2(w2.x, h1, aIF[1]);
                aGO[1] = ffma2(w2.y, h1, aGO[1]);
                aIF[2] = ffma2(w2.x, h2d, aIF[2]);
                aGO[2] = ffma2(w2.y, h2d, aGO[2]);
                aIF[3] = ffma2(w2.x, h3, aIF[3]);
                aGO[3] = ffma2(w2.y, h3, aGO[3]);
            }
        }

        // Store partials: sPif/sPgo ull at [ks][hl][b].
        {
            unsigned long long* pif =
                reinterpret_cast<unsigned long long*>(sPif)
                + (ks * 16 + hl) * 16 + bq * 4;
            unsigned long long* pgo =
                reinterpret_cast<unsigned long long*>(sPgo)
                + (ks * 16 + hl) * 16 + bq * 4;
#pragma unroll
            for (int j = 0; j < 4; ++j) { pif[j] = aIF[j]; pgo[j] = aGO[j]; }
        }
        __syncthreads();

        // Epilogue: thread (eh, eb) sums 4 k-quarter partials (packed adds).
        {
            const unsigned long long* pif =
                reinterpret_cast<const unsigned long long*>(sPif) + eh * 16 + eb;
            const unsigned long long* pgo =
                reinterpret_cast<const unsigned long long*>(sPgo) + eh * 16 + eb;
            unsigned long long sIF = addf2(addf2(pif[0], pif[256]),
                                           addf2(pif[512], pif[768]));
            unsigned long long sGO = addf2(addf2(pgo[0], pgo[256]),
                                           addf2(pgo[512], pgo[768]));
            float ai, af, ag, ao;
            asm("mov.b64 {%0, %1}, %2;" : "=f"(ai), "=f"(af) : "l"(sIF));
            asm("mov.b64 {%0, %1}, %2;" : "=f"(ag), "=f"(ao) : "l"(sGO));
            const float gi = xgCur[(0 * 16 + eh) * GB + eb] + ai;
            const float gf = xgCur[(1 * 16 + eh) * GB + eb] + af;
            const float gg = xgCur[(2 * 16 + eh) * GB + eb] + ag;
            const float go = xgCur[(3 * 16 + eh) * GB + eb] + ao;
            const float is = sigf(gi);
            const float fs = sigf(gf);
            const float gt = tanhf_fast(gg);
            const float os = sigf(go);
            c_state = fs * c_state + is * gt;
            const float h = os * tanhf_fast(c_state);
            hdst[(hrow + eh) * GB + eb] = h;
            if (t < mylen) maxv = fmaxf(maxv, h);
        }
        // Publish h[t+1]: sync (orders all threads' stores), then release.
        __syncthreads();
        if (tid == 0) st_release_gpu(myflag, base + (unsigned)t + 1u);
    }

    g_feat[(hrow + eh) * Bn + bbase + eb] = maxv;
}

// ---------------------------------------------------------------------------
// Kernel 3: classifier  out[b][c] = sum_h feat[h][b] * W_cls[c][h] + b_cls[c]
// ---------------------------------------------------------------------------
__global__ void cls_kernel(const float* __restrict__ Wcls,
                           const float* __restrict__ bcls,
                           float* __restrict__ out) {
    const int tid = threadIdx.x;   // 128 threads
    const int b = tid >> 1, c = tid & 1;
    float s = bcls[c];
#pragma unroll 8
    for (int h = 0; h < Hn; ++h)
        s += g_feat[h * Bn + b] * Wcls[c * Hn + h];
    out[b * 2 + c] = s;
}

// ---------------------------------------------------------------------------
extern "C" void kernel_launch(void* const* d_in, const int* in_sizes, int n_in,
                              void* d_out, int out_size) {
    const int*   x      = (const int*)  d_in[0];  // [64,512] int32
    const int*   length = (const int*)  d_in[1];  // [64,1]   int32
    const float* emb    = (const float*)d_in[2];  // [32000,256]
    const float* Wih    = (const float*)d_in[3];  // [2048,256]
    const float* Whh    = (const float*)d_in[4];  // [2048,512]
    const float* bih    = (const float*)d_in[5];  // [2048]
    const float* bhh    = (const float*)d_in[6];  // [2048]
    const float* Wcls   = (const float*)d_in[7];  // [2,512]
    const float* bcls   = (const float*)d_in[8];  // [2]
    float* out = (float*)d_out;                   // [64,2]

    cudaFuncSetAttribute(lstm_kernel,
                         cudaFuncAttributeMaxDynamicSharedMemorySize, LSTM_SMEM);

    embed_gemm_kernel<<<dim3(16, Tn), 256>>>(x, emb, Wih, bih, bhh);
    lstm_kernel<<<NBLK, NTHR, LSTM_SMEM>>>(Whh, length);
    cls_kernel<<<1, 128>>>(Wcls, bcls, out);
    (void)in_sizes; (void)n_in; (void)out_size;
}